// round 3
// baseline (speedup 1.0000x reference)
#include <cuda_runtime.h>
#include <cuda_bf16.h>

#define RES 7
#define NROI 1024
#define NCH 256
#define CPB 4            // channels per iteration
#define PMAX 1157        // per-channel patch floats (bound ~1056; odd for bank skew)

// ---------------- per-roi precomputed tables ----------------
__device__ int   g_meta[NROI][6];      // lvl, b, py0, px0, pw, ph
__device__ int   g_iyl[NROI][14], g_iyh[NROI][14];   // row idx relative to py0
__device__ int   g_ixl[NROI][14], g_ixh[NROI][14];   // col idx relative to px0
__device__ float g_wyl[NROI][14], g_wyh[NROI][14];
__device__ float g_wxl[NROI][14], g_wxh[NROI][14];

__device__ __forceinline__ void axis_tab(float start, float binsz, int size,
                                         int* lo, int* hi, float* wl, float* wh,
                                         int& mn, int& mx) {
    mn = size - 1; mx = 0;
#pragma unroll
    for (int i = 0; i < 14; i++) {
        float v = start + ((float)i + 0.5f) * 0.5f * binsz;
        bool valid = (v >= -1.0f) && (v <= (float)size);
        float v0 = fmaxf(v, 0.0f);
        int l = (int)floorf(v0);
        int h; float fr;
        if (l >= size - 1) { l = size - 1; h = size - 1; fr = 0.0f; }
        else               { h = l + 1; fr = v0 - (float)l; }
        lo[i] = l; hi[i] = h;
        wl[i] = valid ? (1.0f - fr) : 0.0f;
        wh[i] = valid ? fr : 0.0f;
        mn = min(mn, l); mx = max(mx, h);
    }
}

__global__ void setup_kernel(const float* __restrict__ p0,
                             const float* __restrict__ p1) {
    int r = blockIdx.x * blockDim.x + threadIdx.x;
    if (r >= NROI) return;
    const float* p = (r < 512) ? (p0 + r * 4) : (p1 + (r - 512) * 4);
    float x1 = p[0], y1 = p[1], x2 = p[2], y2 = p[3];
    float area = (x2 - x1 + 1.0f) * (y2 - y1 + 1.0f);
    float sz = sqrtf(area);
    float lv = floorf(4.0f + log2f(sz / 224.0f + 1e-6f));
    lv = fminf(fmaxf(lv, 2.0f), 5.0f);
    int lvl = (int)lv - 2;
    float scale = 0.25f / (float)(1 << lvl);
    int H, W;
    switch (lvl) {
        case 0:  H = 200; W = 200; break;
        case 1:  H = 100; W = 100; break;
        case 2:  H = 50;  W = 50;  break;
        default: H = 25;  W = 25;  break;
    }
    float x1s = x1 * scale, y1s = y1 * scale;
    float rw = fmaxf(x2 * scale - x1s, 1.0f);
    float rh = fmaxf(y2 * scale - y1s, 1.0f);
    float bw = rw / 7.0f, bh = rh / 7.0f;

    int xlo[14], xhi[14], ylo[14], yhi[14];
    float xwl[14], xwh[14], ywl[14], ywh[14];
    int xmn, xmx, ymn, ymx;
    axis_tab(x1s, bw, W, xlo, xhi, xwl, xwh, xmn, xmx);
    axis_tab(y1s, bh, H, ylo, yhi, ywl, ywh, ymn, ymx);

    g_meta[r][0] = lvl;
    g_meta[r][1] = (r < 512) ? 0 : 1;
    g_meta[r][2] = ymn;            // py0
    g_meta[r][3] = xmn;            // px0
    g_meta[r][4] = xmx - xmn + 1;  // pw
    g_meta[r][5] = ymx - ymn + 1;  // ph
#pragma unroll
    for (int i = 0; i < 14; i++) {
        g_ixl[r][i] = xlo[i] - xmn; g_ixh[r][i] = xhi[i] - xmn;
        g_iyl[r][i] = ylo[i] - ymn; g_iyh[r][i] = yhi[i] - ymn;
        g_wxl[r][i] = xwl[i];       g_wxh[r][i] = xwh[i];
        g_wyl[r][i] = ywl[i];       g_wyh[r][i] = ywh[i];
    }
}

// grid = (NROI, 8): blockIdx.x = roi, blockIdx.y = 32-channel chunk.
// Each of 8 iterations stages CPB=4 channel patches in smem, then 196 threads
// compute 4x49 outputs from pure shared-memory bilinear gathers.
__global__ __launch_bounds__(256) void pool_kernel(
    const float* __restrict__ f0, const float* __restrict__ f1,
    const float* __restrict__ f2, const float* __restrict__ f3,
    float* __restrict__ out) {

    __shared__ float patch[CPB][PMAX];

    const int roi = blockIdx.x;
    const int lvl = g_meta[roi][0];
    const int b   = g_meta[roi][1];
    const int py0 = g_meta[roi][2];
    const int px0 = g_meta[roi][3];
    const int pw  = g_meta[roi][4];
    const int ph  = g_meta[roi][5];

    const float* base; int H, W;
    switch (lvl) {
        case 0:  base = f0; H = 200; W = 200; break;
        case 1:  base = f1; H = 100; W = 100; break;
        case 2:  base = f2; H = 50;  W = 50;  break;
        default: base = f3; H = 25;  W = 25;  break;
    }
    const int chanstride = H * W;
    // pointer to (batch b, channel 0) at patch origin
    const float* bbase = base + (size_t)b * NCH * chanstride
                              + (size_t)py0 * W + px0;

    const int tid  = threadIdx.x;
    const int warp = tid >> 5;
    const int lane = tid & 31;
    const int c0_chunk = blockIdx.y * 32;

    // ---- per-thread hoisted interp state (compute threads only) ----
    const bool comp = tid < CPB * 49;
    int cl_c = 0, bin = 0;
    int yo0l = 0, yo0h = 0, yo1l = 0, yo1h = 0;
    int xo0l = 0, xo0h = 0, xo1l = 0, xo1h = 0;
    float wy0l = 0, wy0h = 0, wy1l = 0, wy1h = 0;
    float wx0l = 0, wx0h = 0, wx1l = 0, wx1h = 0;
    if (comp) {
        cl_c = tid / 49; bin = tid - cl_c * 49;
        int py = bin / 7, px = bin - py * 7;
        int sy0 = 2 * py, sy1 = sy0 + 1;
        int sx0 = 2 * px, sx1 = sx0 + 1;
        yo0l = g_iyl[roi][sy0] * pw; yo0h = g_iyh[roi][sy0] * pw;
        yo1l = g_iyl[roi][sy1] * pw; yo1h = g_iyh[roi][sy1] * pw;
        xo0l = g_ixl[roi][sx0];      xo0h = g_ixh[roi][sx0];
        xo1l = g_ixl[roi][sx1];      xo1h = g_ixh[roi][sx1];
        wy0l = g_wyl[roi][sy0]; wy0h = g_wyh[roi][sy0];
        wy1l = g_wyl[roi][sy1]; wy1h = g_wyh[roi][sy1];
        wx0l = g_wxl[roi][sx0]; wx0h = g_wxh[roi][sx0];
        wx1l = g_wxl[roi][sx1]; wx1h = g_wxh[roi][sx1];
    }

    const int nrows = CPB * ph;
    for (int iter = 0; iter < 32 / CPB; iter++) {
        const int cbase_ch = c0_chunk + iter * CPB;
        __syncthreads();   // previous compute done before overwriting patch
        // ---- stage CPB channel patches (coalesced row loads) ----
        for (int j = warp; j < nrows; j += 8) {
            int cl = 0, r = j;
            while (r >= ph) { r -= ph; cl++; }
            const float* src = bbase + (size_t)(cbase_ch + cl) * chanstride
                                     + (size_t)r * W;
            float* dst = &patch[cl][r * pw];
            for (int x = lane; x < pw; x += 32) dst[x] = src[x];
        }
        __syncthreads();
        // ---- compute ----
        if (comp) {
            const float* p = patch[cl_c];
            float acc =
                wy0l * (wx0l * p[yo0l + xo0l] + wx0h * p[yo0l + xo0h]) +
                wy0h * (wx0l * p[yo0h + xo0l] + wx0h * p[yo0h + xo0h]) +
                wy0l * (wx1l * p[yo0l + xo1l] + wx1h * p[yo0l + xo1h]) +
                wy0h * (wx1l * p[yo0h + xo1l] + wx1h * p[yo0h + xo1h]) +
                wy1l * (wx0l * p[yo1l + xo0l] + wx0h * p[yo1l + xo0h]) +
                wy1h * (wx0l * p[yo1h + xo0l] + wx0h * p[yo1h + xo0h]) +
                wy1l * (wx1l * p[yo1l + xo1l] + wx1h * p[yo1l + xo1h]) +
                wy1h * (wx1l * p[yo1h + xo1l] + wx1h * p[yo1h + xo1h]);
            out[((size_t)roi * NCH + cbase_ch + cl_c) * 49 + bin] = acc * 0.25f;
        }
    }
}

extern "C" void kernel_launch(void* const* d_in, const int* in_sizes, int n_in,
                              void* d_out, int out_size) {
    const float* f0 = (const float*)d_in[0];
    const float* f1 = (const float*)d_in[1];
    const float* f2 = (const float*)d_in[2];
    const float* f3 = (const float*)d_in[3];
    // d_in[4] = feat4 (13x13) — never selected by the 4 RATIOS; unused.
    const float* p0 = (const float*)d_in[5];
    const float* p1 = (const float*)d_in[6];
    float* out = (float*)d_out;

    setup_kernel<<<4, 256>>>(p0, p1);
    dim3 grid(NROI, 8);
    pool_kernel<<<grid, 256>>>(f0, f1, f2, f3, out);
}

// round 4
// speedup vs baseline: 4.8128x; 4.8128x over previous
#include <cuda_runtime.h>
#include <cuda_bf16.h>

#define RES 7
#define NROI 1024
#define NCH 256

// ---------------- per-roi precomputed tables ----------------
// lvl + batch packed
__device__ int2   g_lb[NROI];
// per (roi, py): 4 row indices (yl0,yh0,yl1,yh1) and weights (*0.5, validity-folded)
__device__ int4   g_yrow[NROI][8];
__device__ float4 g_ywt[NROI][8];
// per (roi, px): 4 col indices and weights (*0.5)
__device__ int4   g_xcol[NROI][8];
__device__ float4 g_xwt[NROI][8];

// one sample point: clamped lo/hi + weights with validity folded
__device__ __forceinline__ void samp(float v, int size,
                                     int& lo, int& hi, float& wl, float& wh) {
    bool valid = (v >= -1.0f) && (v <= (float)size);
    float v0 = fmaxf(v, 0.0f);
    int l = (int)floorf(v0);
    float fr;
    if (l >= size - 1) { l = size - 1; hi = size - 1; fr = 0.0f; }
    else               { hi = l + 1; fr = v0 - (float)l; }
    lo = l;
    wl = valid ? (1.0f - fr) : 0.0f;
    wh = valid ? fr : 0.0f;
}

__global__ void setup_kernel(const float* __restrict__ p0,
                             const float* __restrict__ p1) {
    int r = blockIdx.x * blockDim.x + threadIdx.x;
    if (r >= NROI) return;
    const float* p = (r < 512) ? (p0 + r * 4) : (p1 + (r - 512) * 4);
    float x1 = p[0], y1 = p[1], x2 = p[2], y2 = p[3];
    float area = (x2 - x1 + 1.0f) * (y2 - y1 + 1.0f);
    float sz = sqrtf(area);
    float lv = floorf(4.0f + log2f(sz / 224.0f + 1e-6f));
    lv = fminf(fmaxf(lv, 2.0f), 5.0f);
    int lvl = (int)lv - 2;
    float scale = 0.25f / (float)(1 << lvl);
    int H, W;
    switch (lvl) {
        case 0:  H = 200; W = 200; break;
        case 1:  H = 100; W = 100; break;
        case 2:  H = 50;  W = 50;  break;
        default: H = 25;  W = 25;  break;
    }
    float x1s = x1 * scale, y1s = y1 * scale;
    float rw = fmaxf(x2 * scale - x1s, 1.0f);
    float rh = fmaxf(y2 * scale - y1s, 1.0f);
    float bw = rw / 7.0f, bh = rh / 7.0f;

    g_lb[r] = make_int2(lvl, (r < 512) ? 0 : 1);

#pragma unroll
    for (int q = 0; q < 7; q++) {
        // y axis, samples 2q, 2q+1
        {
            float s0 = y1s + ((float)(2 * q) + 0.5f) * 0.5f * bh;
            float s1 = y1s + ((float)(2 * q + 1) + 0.5f) * 0.5f * bh;
            int l0, h0, l1, h1; float a0, b0, a1, b1;
            samp(s0, H, l0, h0, a0, b0);
            samp(s1, H, l1, h1, a1, b1);
            g_yrow[r][q] = make_int4(l0, h0, l1, h1);
            g_ywt[r][q]  = make_float4(a0 * 0.5f, b0 * 0.5f, a1 * 0.5f, b1 * 0.5f);
        }
        // x axis
        {
            float s0 = x1s + ((float)(2 * q) + 0.5f) * 0.5f * bw;
            float s1 = x1s + ((float)(2 * q + 1) + 0.5f) * 0.5f * bw;
            int l0, h0, l1, h1; float a0, b0, a1, b1;
            samp(s0, W, l0, h0, a0, b0);
            samp(s1, W, l1, h1, a1, b1);
            g_xcol[r][q] = make_int4(l0, h0, l1, h1);
            g_xwt[r][q]  = make_float4(a0 * 0.5f, b0 * 0.5f, a1 * 0.5f, b1 * 0.5f);
        }
    }
}

// grid = (49, NROI): blockIdx.y = roi; 256 threads; e in [0, 12544) = (c, bin).
__global__ __launch_bounds__(256) void pool_kernel(
    const float* __restrict__ f0, const float* __restrict__ f1,
    const float* __restrict__ f2, const float* __restrict__ f3,
    float* __restrict__ out) {
    const int roi = blockIdx.y;
    const int e = blockIdx.x * 256 + threadIdx.x;   // [0, 12544)
    const int c = e / 49;
    const int bin = e - c * 49;
    const int py = bin / 7;
    const int px = bin - py * 7;

    const int2 lb = g_lb[roi];
    const float* base; int H, W;
    switch (lb.x) {
        case 0:  base = f0; H = 200; W = 200; break;
        case 1:  base = f1; H = 100; W = 100; break;
        case 2:  base = f2; H = 50;  W = 50;  break;
        default: base = f3; H = 25;  W = 25;  break;
    }

    const int4   yr = g_yrow[roi][py];
    const float4 wy = g_ywt[roi][py];
    const int4   xc = g_xcol[roi][px];
    const float4 wx = g_xwt[roi][px];

    const float* cbase = base + ((size_t)lb.y * NCH + c) * (H * W);
    const float* r0 = cbase + yr.x * W;
    const float* r1 = cbase + yr.y * W;
    const float* r2 = cbase + yr.z * W;
    const float* r3 = cbase + yr.w * W;

    // row-wise horizontal interp, then vertical combine (weights pre-scaled by 0.5 each axis)
    float s0 = wx.x * __ldg(r0 + xc.x) + wx.y * __ldg(r0 + xc.y)
             + wx.z * __ldg(r0 + xc.z) + wx.w * __ldg(r0 + xc.w);
    float s1 = wx.x * __ldg(r1 + xc.x) + wx.y * __ldg(r1 + xc.y)
             + wx.z * __ldg(r1 + xc.z) + wx.w * __ldg(r1 + xc.w);
    float s2 = wx.x * __ldg(r2 + xc.x) + wx.y * __ldg(r2 + xc.y)
             + wx.z * __ldg(r2 + xc.z) + wx.w * __ldg(r2 + xc.w);
    float s3 = wx.x * __ldg(r3 + xc.x) + wx.y * __ldg(r3 + xc.y)
             + wx.z * __ldg(r3 + xc.z) + wx.w * __ldg(r3 + xc.w);

    float acc = wy.x * s0 + wy.y * s1 + wy.z * s2 + wy.w * s3;

    out[((size_t)roi * NCH + c) * 49 + bin] = acc;
}

extern "C" void kernel_launch(void* const* d_in, const int* in_sizes, int n_in,
                              void* d_out, int out_size) {
    const float* f0 = (const float*)d_in[0];
    const float* f1 = (const float*)d_in[1];
    const float* f2 = (const float*)d_in[2];
    const float* f3 = (const float*)d_in[3];
    // d_in[4] = feat4 (13x13) — never selected by the 4 RATIOS; unused.
    const float* p0 = (const float*)d_in[5];
    const float* p1 = (const float*)d_in[6];
    float* out = (float*)d_out;

    setup_kernel<<<4, 256>>>(p0, p1);
    dim3 grid(49, NROI);
    pool_kernel<<<grid, 256>>>(f0, f1, f2, f3, out);
}